// round 1
// baseline (speedup 1.0000x reference)
#include <cuda_runtime.h>
#include <cuda_bf16.h>
#include <cstdint>

// ============================================================================
// YukarinSa f0 predictor: table-folded encoder + persistent-grid GRU scan.
//
// L=8192 steps, H=1024, 3H=3072.
//
// Precompute:  U[1024x51] = enc_W @ [emb^T | accent cols | spk-const]
//              V[3072x51] = Wih_h @ U     (T table | A cols | c0)
// Scan:        128 CTAs x 8 warps; warp w of CTA b owns h-dim d = 8b+w.
//              Whh rows {d, d+1024, d+2048} + post_W live in registers as
//              packed f32x2 pairs. Per step: load h(t-1) (ld.cg, double
//              buffered in global), 4 packed dots, shfl reduce, gate math on
//              lane 0, store h_new, release/acquire grid barrier.
// ============================================================================

#define L_STEPS 8192
#define NCTA    128

typedef unsigned long long ull;

__device__ float    g_hbuf[2][1024];
__device__ float    g_U[51 * 1024];   // [p][i] layout
__device__ float    g_V[3072 * 51];   // [r][col] layout: cols 0..45 = T, 46..49 = A, 50 = c0 (no bih)
__device__ unsigned g_rec[L_STEPS];
__device__ unsigned g_bar_cnt;
__device__ unsigned g_bar_gen;

// ---------------------------------------------------------------- PTX helpers
__device__ __forceinline__ ull ffma2(ull a, ull b, ull c) {
    ull d;
    asm("fma.rn.f32x2 %0, %1, %2, %3;" : "=l"(d) : "l"(a), "l"(b), "l"(c));
    return d;
}
__device__ __forceinline__ ull ldcg64(const ull* p) {
    ull v;
    asm volatile("ld.global.cg.b64 %0, [%1];" : "=l"(v) : "l"(p));
    return v;
}
__device__ __forceinline__ void st_cg_f32(float* p, float v) {
    asm volatile("st.global.cg.f32 [%0], %1;" :: "l"(p), "f"(v) : "memory");
}
__device__ __forceinline__ unsigned ld_acq(const unsigned* p) {
    unsigned v;
    asm volatile("ld.acquire.gpu.global.u32 %0, [%1];" : "=r"(v) : "l"(p));
    return v;
}
__device__ __forceinline__ void st_rel(unsigned* p, unsigned v) {
    asm volatile("st.release.gpu.global.u32 [%0], %1;" :: "l"(p), "r"(v) : "memory");
}
__device__ __forceinline__ void st_rlx(unsigned* p, unsigned v) {
    asm volatile("st.relaxed.gpu.global.u32 [%0], %1;" :: "l"(p), "r"(v) : "memory");
}
__device__ __forceinline__ unsigned atom_add_rel(unsigned* p, unsigned v) {
    unsigned o;
    asm volatile("atom.release.gpu.global.add.u32 %0, [%1], %2;"
                 : "=r"(o) : "l"(p), "r"(v) : "memory");
    return o;
}

__device__ __forceinline__ float fast_sig(float x) {
    float e = __expf(-x);
    return __fdividef(1.f, 1.f + e);
}
__device__ __forceinline__ float fast_tanh(float x) {
    float e = __expf(2.f * x);           // x large+ -> inf -> 1; x large- -> 0 -> -1
    return 1.f - __fdividef(2.f, e + 1.f);
}

union F2u { ull u; float2 f; };

// ---------------------------------------------------------------- K0: pack/reset
__global__ void k0_pack(const int* __restrict__ v, const int* __restrict__ c,
                        const int* __restrict__ sa, const int* __restrict__ ea,
                        const int* __restrict__ sap, const int* __restrict__ eap) {
    int i = blockIdx.x * 256 + threadIdx.x;
    if (i < L_STEPS) {
        unsigned r = (unsigned)(v[i] + 1) | ((unsigned)(c[i] + 1) << 8)
                   | ((unsigned)(sa[i]  & 1) << 16) | ((unsigned)(ea[i]  & 1) << 17)
                   | ((unsigned)(sap[i] & 1) << 18) | ((unsigned)(eap[i] & 1) << 19);
        g_rec[i] = r;
        if (i < 2048) ((float*)g_hbuf)[i] = 0.f;
        if (i == 0) { g_bar_cnt = 0; g_bar_gen = 0; }
    }
}

// ---------------------------------------------------------------- K1a: U = encW-side fold
__global__ void k1a_U(const float* __restrict__ encW, const float* __restrict__ encb,
                      const float* __restrict__ emb,  const float* __restrict__ spkemb,
                      const int* __restrict__ sid) {
    __shared__ float ew[516];
    int i = blockIdx.x;                    // 0..1023 (enc hidden row)
    int tid = threadIdx.x;                 // 64 threads
    for (int n = tid; n < 516; n += 64) ew[n] = encW[i * 516 + n];
    __syncthreads();
    if (tid < 46) {
        const float* er = emb + tid * 256;
        float s = 0.f;
        for (int e = 0; e < 256; ++e) s = fmaf(ew[e], er[e], s);
        g_U[tid * 1024 + i] = s;
    } else if (tid < 50) {
        g_U[tid * 1024 + i] = ew[256 + (tid - 46)];
    } else if (tid == 50) {
        const float* sr = spkemb + (size_t)sid[0] * 256;
        float s = encb[i];
        for (int e = 0; e < 256; ++e) s = fmaf(ew[260 + e], sr[e], s);
        g_U[50 * 1024 + i] = s;
    }
}

// ---------------------------------------------------------------- K1b: V = Wih_h @ U
__global__ void k1b_V(const float* __restrict__ Wih) {
    __shared__ float Ws[32][129];
    __shared__ float Us[56][128];
    int tid = threadIdx.x;
    int r = tid & 31, pg = tid >> 5;
    int R0 = blockIdx.x * 32;
    float acc[7] = {0.f, 0.f, 0.f, 0.f, 0.f, 0.f, 0.f};
    for (int k0 = 0; k0 < 1024; k0 += 128) {
        for (int n = tid; n < 32 * 128; n += 256) {
            int rr = n >> 7, cc = n & 127;
            Ws[rr][cc] = Wih[(size_t)(R0 + rr) * 1025 + k0 + cc];
        }
        for (int n = tid; n < 56 * 128; n += 256) {
            int pp = n >> 7, cc = n & 127;
            Us[pp][cc] = (pp < 51) ? g_U[pp * 1024 + k0 + cc] : 0.f;
        }
        __syncthreads();
        #pragma unroll 4
        for (int kk = 0; kk < 128; ++kk) {
            float wv = Ws[r][kk];
            #pragma unroll
            for (int j = 0; j < 7; ++j)
                acc[j] = fmaf(wv, Us[pg + 8 * j][kk], acc[j]);
        }
        __syncthreads();
    }
    #pragma unroll
    for (int j = 0; j < 7; ++j) {
        int p = pg + 8 * j;
        if (p < 51) g_V[(size_t)(R0 + r) * 51 + p] = acc[j];
    }
}

// ---------------------------------------------------------------- K3: persistent scan
__global__ void __launch_bounds__(256, 1)
k3_scan(const float* __restrict__ Wih, const float* __restrict__ Whh,
        const float* __restrict__ bih, const float* __restrict__ bhh,
        const float* __restrict__ postW, const float* __restrict__ postb,
        float* __restrict__ out) {
    __shared__ unsigned rec_s[L_STEPS];
    __shared__ float Ts[3][8][46];
    __shared__ float Ac[3][8][16];

    const int tid  = threadIdx.x;
    const int w    = tid >> 5;
    const int lane = tid & 31;
    const int cta  = blockIdx.x;
    const int d    = cta * 8 + w;          // owned h-dim

    // --- register-resident weights: pairs (cols 64k+2*lane, +1), k=0..15 ---
    ull wr[16], wz[16], wn[16], wp[16];
    {
        const ull* pr = (const ull*)(Whh + (size_t)d          * 1024) + lane;
        const ull* pz = (const ull*)(Whh + (size_t)(1024 + d) * 1024) + lane;
        const ull* pn = (const ull*)(Whh + (size_t)(2048 + d) * 1024) + lane;
        const ull* pp = (const ull*)(postW) + lane;
        #pragma unroll
        for (int k = 0; k < 16; ++k) {
            wr[k] = pr[32 * k]; wz[k] = pz[32 * k];
            wn[k] = pn[32 * k]; wp[k] = pp[32 * k];
        }
    }
    const float b_r  = bhh[d], b_z = bhh[1024 + d], b_n = bhh[2048 + d];
    const float wf0r = Wih[(size_t)d          * 1025 + 1024];
    const float wf0z = Wih[(size_t)(1024 + d) * 1025 + 1024];
    const float wf0n = Wih[(size_t)(2048 + d) * 1025 + 1024];
    const float pb   = postb[0];

    // --- shared tables ---
    for (int n = tid; n < L_STEPS; n += 256) rec_s[n] = g_rec[n];
    for (int n = tid; n < 3 * 8 * 46; n += 256) {
        int g = n / 368, rm = n - g * 368, w2 = rm / 46, p = rm - w2 * 46;
        Ts[g][w2][p] = g_V[(size_t)(cta * 8 + w2 + g * 1024) * 51 + p];
    }
    #pragma unroll
    for (int g = 0; g < 3; ++g) {
        int r = d + g * 1024;
        if (lane < 16) {
            float val = g_V[(size_t)r * 51 + 50] + bih[r];
            if (lane & 1) val += g_V[(size_t)r * 51 + 46];
            if (lane & 2) val += g_V[(size_t)r * 51 + 47];
            if (lane & 4) val += g_V[(size_t)r * 51 + 48];
            if (lane & 8) val += g_V[(size_t)r * 51 + 49];
            Ac[g][w][lane] = val;
        }
    }
    __syncthreads();

    float hprev = 0.f;
    const ull* hb0 = (const ull*)(&g_hbuf[0][0]) + lane;
    const ull* hb1 = (const ull*)(&g_hbuf[1][0]) + lane;

    for (int t = 0; t < L_STEPS; ++t) {
        if (t > 0 && lane == 0) {
            while ((int)ld_acq(&g_bar_gen) < t) { }
        }
        __syncwarp();
        const ull* hb = (t & 1) ? hb1 : hb0;
        ull ar = 0ull, az = 0ull, an = 0ull, ap = 0ull;
        #pragma unroll
        for (int k = 0; k < 16; ++k) {
            ull hv = ldcg64(hb + 32 * k);
            ar = ffma2(wr[k], hv, ar);
            az = ffma2(wz[k], hv, az);
            an = ffma2(wn[k], hv, an);
            ap = ffma2(wp[k], hv, ap);
        }
        F2u u;
        u.u = ar; float sr = u.f.x + u.f.y;
        u.u = az; float sz = u.f.x + u.f.y;
        u.u = an; float sn = u.f.x + u.f.y;
        u.u = ap; float sp = u.f.x + u.f.y;
        #pragma unroll
        for (int m = 16; m >= 1; m >>= 1) {
            sr += __shfl_xor_sync(0xffffffffu, sr, m);
            sz += __shfl_xor_sync(0xffffffffu, sz, m);
            sn += __shfl_xor_sync(0xffffffffu, sn, m);
            sp += __shfl_xor_sync(0xffffffffu, sp, m);
        }
        if (lane == 0) {
            unsigned rc = rec_s[t];
            int vi = rc & 255, ci = (rc >> 8) & 255, mk = (rc >> 16) & 15;
            float f0p = (t > 0) ? (sp + pb) : 0.f;
            float gir = Ts[0][w][vi] + Ts[0][w][ci] + Ac[0][w][mk] + f0p * wf0r;
            float giz = Ts[1][w][vi] + Ts[1][w][ci] + Ac[1][w][mk] + f0p * wf0z;
            float gin = Ts[2][w][vi] + Ts[2][w][ci] + Ac[2][w][mk] + f0p * wf0n;
            float rr = fast_sig(gir + sr + b_r);
            float zz = fast_sig(giz + sz + b_z);
            float nn = fast_tanh(gin + rr * (sn + b_n));
            float hn = (1.f - zz) * nn + zz * hprev;
            hprev = hn;
            st_cg_f32(&g_hbuf[(t + 1) & 1][d], hn);
            if (d == 0 && t > 0) out[t - 1] = f0p;
        }
        __syncthreads();
        if (tid == 0) {
            unsigned old = atom_add_rel(&g_bar_cnt, 1u);
            if (old == NCTA - 1) {
                st_rlx(&g_bar_cnt, 0u);
                st_rel(&g_bar_gen, (unsigned)(t + 1));
            }
        }
    }

    // epilogue: f0(L-1) from h(L-1) (in buf 0)
    if (cta == 0 && w == 0) {
        if (lane == 0) {
            while ((int)ld_acq(&g_bar_gen) < L_STEPS) { }
        }
        __syncwarp();
        ull ap = 0ull;
        #pragma unroll
        for (int k = 0; k < 16; ++k) {
            ull hv = ldcg64(hb0 + 32 * k);
            ap = ffma2(wp[k], hv, ap);
        }
        F2u u; u.u = ap; float sp = u.f.x + u.f.y;
        #pragma unroll
        for (int m = 16; m >= 1; m >>= 1)
            sp += __shfl_xor_sync(0xffffffffu, sp, m);
        if (lane == 0) out[L_STEPS - 1] = sp + pb;
    }
}

// ---------------------------------------------------------------- launch
extern "C" void kernel_launch(void* const* d_in, const int* in_sizes, int n_in,
                              void* d_out, int out_size) {
    (void)in_sizes; (void)n_in; (void)out_size;
    const int*   vowel = (const int*)d_in[1];
    const int*   cons  = (const int*)d_in[2];
    const int*   sa    = (const int*)d_in[3];
    const int*   ea    = (const int*)d_in[4];
    const int*   sap   = (const int*)d_in[5];
    const int*   eap   = (const int*)d_in[6];
    const int*   sid   = (const int*)d_in[7];
    const float* emb   = (const float*)d_in[8];
    const float* spke  = (const float*)d_in[9];
    const float* encW  = (const float*)d_in[10];
    const float* encb  = (const float*)d_in[11];
    const float* Wih   = (const float*)d_in[12];
    const float* Whh   = (const float*)d_in[13];
    const float* bih   = (const float*)d_in[14];
    const float* bhh   = (const float*)d_in[15];
    const float* postW = (const float*)d_in[16];
    const float* postb = (const float*)d_in[17];
    float* out = (float*)d_out;

    k0_pack<<<L_STEPS / 256, 256>>>(vowel, cons, sa, ea, sap, eap);
    k1a_U<<<1024, 64>>>(encW, encb, emb, spke, sid);
    k1b_V<<<96, 256>>>(Wih);
    k3_scan<<<NCTA, 256>>>(Wih, Whh, bih, bhh, postW, postb, out);
}